// round 3
// baseline (speedup 1.0000x reference)
#include <cuda_runtime.h>
#include <cstdint>
#include <cstddef>

#define BATCH 64
#define TDEC  256
#define TENC  1152
#define MELD  80
#define ATTD  128
#define RNND  1024
#define GATE4 4096
#define KX    1280
#define ROWS  16384

#define MELS_CNT   (BATCH*TDEC*MELD)
#define GATES_OFF  MELS_CNT
#define ALIGNS_OFF (MELS_CNT + BATCH*TDEC)

__device__ float g_Pin[ROWS * MELD];
__device__ float g_P1 [ROWS * 256];
__device__ float g_P2 [ROWS * 256];
__device__ float g_Q  [ROWS * ATTD];
__device__ float g_PM [BATCH * TENC * ATTD];
__device__ float g_E  [(size_t)ROWS * TENC];
__device__ float g_X  [(size_t)ROWS * KX];
__device__ float g_G1 [(size_t)ROWS * GATE4];
__device__ float g_H  [(size_t)ROWS * RNND];
__device__ float g_C  [BATCH * RNND];

__global__ void zero_kernel(float* p, int n) {
    int i = blockIdx.x * blockDim.x + threadIdx.x;
    if (i < n) p[i] = 0.f;
}

__global__ void prep_pin_kernel(const float* __restrict__ mel, float* __restrict__ Pin) {
    int i = blockIdx.x * blockDim.x + threadIdx.x;
    if (i < ROWS * MELD) {
        int r = i / MELD, m = i - r * MELD;
        int t = r >> 6, b = r & 63;
        Pin[i] = (t == 0) ? 0.f : mel[((size_t)b * TDEC + t) * MELD + m];
    }
}

// C[M,N] = act(A[M,K]@B[K,N] + bias1 + bias2). M%128==0, K%8==0, N guarded.
__global__ __launch_bounds__(256, 2) void sgemm_kernel(
    const float* __restrict__ A, int lda,
    const float* __restrict__ B, int ldb,
    float* __restrict__ C, int ldc,
    int M, int N, int K,
    const float* __restrict__ bias1, const float* __restrict__ bias2,
    int relu, int rowperm)
{
    __shared__ float As[8][128];
    __shared__ float Bs[8][128];
    int bm = blockIdx.y * 128, bn = blockIdx.x * 128;
    int tid = threadIdx.x;
    int tx = tid & 15, ty = tid >> 4;
    float acc[8][8];
#pragma unroll
    for (int i = 0; i < 8; i++)
#pragma unroll
        for (int j = 0; j < 8; j++) acc[i][j] = 0.f;

    int a_row = tid >> 1, a_k4 = (tid & 1) * 4;
    int b_kk = tid >> 5, b_c4 = (tid & 31) * 4;

    for (int k0 = 0; k0 < K; k0 += 8) {
        float4 av = *reinterpret_cast<const float4*>(A + (size_t)(bm + a_row) * lda + k0 + a_k4);
        float4 bv = make_float4(0.f, 0.f, 0.f, 0.f);
        if (bn + b_c4 < N)
            bv = *reinterpret_cast<const float4*>(B + (size_t)(k0 + b_kk) * ldb + bn + b_c4);
        __syncthreads();
        As[a_k4 + 0][a_row] = av.x; As[a_k4 + 1][a_row] = av.y;
        As[a_k4 + 2][a_row] = av.z; As[a_k4 + 3][a_row] = av.w;
        *reinterpret_cast<float4*>(&Bs[b_kk][b_c4]) = bv;
        __syncthreads();
#pragma unroll
        for (int kk = 0; kk < 8; kk++) {
            float ar[8], br[8];
            float4 a0 = *reinterpret_cast<const float4*>(&As[kk][ty * 8]);
            float4 a1 = *reinterpret_cast<const float4*>(&As[kk][ty * 8 + 4]);
            float4 b0 = *reinterpret_cast<const float4*>(&Bs[kk][tx * 8]);
            float4 b1 = *reinterpret_cast<const float4*>(&Bs[kk][tx * 8 + 4]);
            ar[0]=a0.x;ar[1]=a0.y;ar[2]=a0.z;ar[3]=a0.w;ar[4]=a1.x;ar[5]=a1.y;ar[6]=a1.z;ar[7]=a1.w;
            br[0]=b0.x;br[1]=b0.y;br[2]=b0.z;br[3]=b0.w;br[4]=b1.x;br[5]=b1.y;br[6]=b1.z;br[7]=b1.w;
#pragma unroll
            for (int i = 0; i < 8; i++)
#pragma unroll
                for (int j = 0; j < 8; j++)
                    acc[i][j] = fmaf(ar[i], br[j], acc[i][j]);
        }
    }
#pragma unroll
    for (int i = 0; i < 8; i++) {
        int row = bm + ty * 8 + i;
        int orow = rowperm ? ((row & 63) * TDEC + (row >> 6)) : row;
#pragma unroll
        for (int j = 0; j < 8; j++) {
            int col = bn + tx * 8 + j;
            if (col < N) {
                float v = acc[i][j];
                if (bias1) v += bias1[col];
                if (bias2) v += bias2[col];
                if (relu)  v = fmaxf(v, 0.f);
                C[(size_t)orow * ldc + col] = v;
            }
        }
    }
}

// E[t*64+b][te] = sum_d v[d] * tanh(Q[t*64+b][d] + PM[b][te][d])
__global__ __launch_bounds__(256) void att_e_kernel(
    const float* __restrict__ Q, const float* __restrict__ PM,
    const float* __restrict__ v, float* __restrict__ E)
{
    __shared__ float pm_s[64][129];
    __shared__ float qs[4][128];
    __shared__ float v_s[128];
    int b = blockIdx.y, te0 = blockIdx.x * 64, tid = threadIdx.x;
    if (tid < 128) v_s[tid] = v[tid];
    for (int i = tid; i < 64 * 128; i += 256) {
        int r = i >> 7, c = i & 127;
        pm_s[r][c] = PM[((size_t)b * TENC + te0 + r) * ATTD + c];
    }
    int te = tid & 63, qq = tid >> 6;
    __syncthreads();
    for (int t0 = 0; t0 < TDEC; t0 += 4) {
        for (int i = tid; i < 4 * 128; i += 256) {
            int q = i >> 7, c = i & 127;
            qs[q][c] = Q[((size_t)(t0 + q) * 64 + b) * ATTD + c];
        }
        __syncthreads();
        float e = 0.f;
#pragma unroll 4
        for (int d = 0; d < 128; d++) {
            float x = qs[qq][d] + pm_s[te][d];
            float th;
            asm("tanh.approx.f32 %0, %1;" : "=f"(th) : "f"(x));
            e = fmaf(v_s[d], th, e);
        }
        E[((size_t)(t0 + qq) * 64 + b) * TENC + te0 + te] = e;
        __syncthreads();
    }
}

// softmax over te, write aligns + X = [ctx | w]
__global__ __launch_bounds__(256) void att_softmax_ctx_kernel(
    const float* __restrict__ E, const float* __restrict__ PM,
    float* __restrict__ X, float* __restrict__ aligns)
{
    __shared__ float w_s[8][TENC];
    __shared__ float inv_s[8];
    int b = blockIdx.y, t0 = blockIdx.x * 8, tid = threadIdx.x;
    int warp = tid >> 5, lane = tid & 31;
    {
        int t = t0 + warp;
        size_t eb = ((size_t)t * 64 + b) * TENC;
        float m = -1e30f;
        for (int te = lane; te < TENC; te += 32) m = fmaxf(m, E[eb + te]);
#pragma unroll
        for (int o = 16; o; o >>= 1) m = fmaxf(m, __shfl_xor_sync(0xffffffffu, m, o));
        float s = 0.f;
        for (int te = lane; te < TENC; te += 32) {
            float w = __expf(E[eb + te] - m);
            w_s[warp][te] = w; s += w;
        }
#pragma unroll
        for (int o = 16; o; o >>= 1) s += __shfl_xor_sync(0xffffffffu, s, o);
        if (lane == 0) inv_s[warp] = 1.f / s;
    }
    __syncthreads();
    for (int i = tid; i < 8 * TENC; i += 256) {
        int q = i / TENC, te = i - q * TENC;
        float wv = w_s[q][te] * inv_s[q];
        int t = t0 + q;
        aligns[((size_t)b * TDEC + t) * TENC + te] = wv;
        X[((size_t)t * 64 + b) * KX + ATTD + te] = wv;
    }
    int d = tid & 127, qh = tid >> 7;
    float a0 = 0.f, a1 = 0.f, a2 = 0.f, a3 = 0.f;
#pragma unroll 4
    for (int te = 0; te < TENC; te++) {
        float pmv = PM[((size_t)b * TENC + te) * ATTD + d];
        a0 = fmaf(w_s[qh * 4 + 0][te], pmv, a0);
        a1 = fmaf(w_s[qh * 4 + 1][te], pmv, a1);
        a2 = fmaf(w_s[qh * 4 + 2][te], pmv, a2);
        a3 = fmaf(w_s[qh * 4 + 3][te], pmv, a3);
    }
    X[((size_t)(t0 + qh*4 + 0) * 64 + b) * KX + d] = a0 * inv_s[qh*4 + 0];
    X[((size_t)(t0 + qh*4 + 1) * 64 + b) * KX + d] = a1 * inv_s[qh*4 + 1];
    X[((size_t)(t0 + qh*4 + 2) * 64 + b) * KX + d] = a2 * inv_s[qh*4 + 2];
    X[((size_t)(t0 + qh*4 + 3) * 64 + b) * KX + d] = a3 * inv_s[qh*4 + 3];
}

// one recurrence step: gates = G1[t] + h_{t-1}@Whh; pointwise LSTM
__global__ __launch_bounds__(128) void lstm_step_kernel(
    const float* __restrict__ G1, const float* __restrict__ Whh,
    float* __restrict__ H, float* __restrict__ C, int t)
{
    __shared__ float h_s[32][33];
    __shared__ float w_s[32][4][16];
    int b0 = (blockIdx.x & 1) * 32;
    int u0 = (blockIdx.x >> 1) * 16;
    int tid = threadIdx.x;
    int u = tid & 15, bg = tid >> 4;
    float acc[4][4];
#pragma unroll
    for (int i = 0; i < 4; i++)
#pragma unroll
        for (int j = 0; j < 4; j++) acc[i][j] = 0.f;

    if (t > 0) {
        const float* hp = H + (size_t)(t - 1) * 64 * RNND;
        int lr = tid >> 2, lc = (tid & 3) * 8;
        int wk = tid >> 2, wg = tid & 3;
        for (int k0 = 0; k0 < RNND; k0 += 32) {
            float4 h0 = *reinterpret_cast<const float4*>(hp + (size_t)(b0 + lr) * RNND + k0 + lc);
            float4 h1 = *reinterpret_cast<const float4*>(hp + (size_t)(b0 + lr) * RNND + k0 + lc + 4);
            const float* wp = Whh + (size_t)(k0 + wk) * GATE4 + wg * RNND + u0;
            float4 w0 = *reinterpret_cast<const float4*>(wp);
            float4 w1 = *reinterpret_cast<const float4*>(wp + 4);
            float4 w2 = *reinterpret_cast<const float4*>(wp + 8);
            float4 w3 = *reinterpret_cast<const float4*>(wp + 12);
            __syncthreads();
            h_s[lr][lc+0]=h0.x; h_s[lr][lc+1]=h0.y; h_s[lr][lc+2]=h0.z; h_s[lr][lc+3]=h0.w;
            h_s[lr][lc+4]=h1.x; h_s[lr][lc+5]=h1.y; h_s[lr][lc+6]=h1.z; h_s[lr][lc+7]=h1.w;
            float4* wsp = reinterpret_cast<float4*>(&w_s[wk][wg][0]);
            wsp[0]=w0; wsp[1]=w1; wsp[2]=w2; wsp[3]=w3;
            __syncthreads();
#pragma unroll
            for (int k = 0; k < 32; k++) {
                float hv0 = h_s[bg*4+0][k], hv1 = h_s[bg*4+1][k];
                float hv2 = h_s[bg*4+2][k], hv3 = h_s[bg*4+3][k];
                float wv0 = w_s[k][0][u], wv1 = w_s[k][1][u];
                float wv2 = w_s[k][2][u], wv3 = w_s[k][3][u];
                acc[0][0]=fmaf(hv0,wv0,acc[0][0]); acc[0][1]=fmaf(hv0,wv1,acc[0][1]);
                acc[0][2]=fmaf(hv0,wv2,acc[0][2]); acc[0][3]=fmaf(hv0,wv3,acc[0][3]);
                acc[1][0]=fmaf(hv1,wv0,acc[1][0]); acc[1][1]=fmaf(hv1,wv1,acc[1][1]);
                acc[1][2]=fmaf(hv1,wv2,acc[1][2]); acc[1][3]=fmaf(hv1,wv3,acc[1][3]);
                acc[2][0]=fmaf(hv2,wv0,acc[2][0]); acc[2][1]=fmaf(hv2,wv1,acc[2][1]);
                acc[2][2]=fmaf(hv2,wv2,acc[2][2]); acc[2][3]=fmaf(hv2,wv3,acc[2][3]);
                acc[3][0]=fmaf(hv3,wv0,acc[3][0]); acc[3][1]=fmaf(hv3,wv1,acc[3][1]);
                acc[3][2]=fmaf(hv3,wv2,acc[3][2]); acc[3][3]=fmaf(hv3,wv3,acc[3][3]);
            }
        }
    }
#pragma unroll
    for (int bi = 0; bi < 4; bi++) {
        int b = b0 + bg * 4 + bi;
        int unit = u0 + u;
        size_t gr = ((size_t)t * 64 + b) * GATE4;
        float gi = acc[bi][0] + G1[gr + 0*RNND + unit];
        float gf = acc[bi][1] + G1[gr + 1*RNND + unit];
        float gg = acc[bi][2] + G1[gr + 2*RNND + unit];
        float go = acc[bi][3] + G1[gr + 3*RNND + unit];
        float i_ = 1.f / (1.f + __expf(-gi));
        float f_ = 1.f / (1.f + __expf(-gf));
        float g_ = tanhf(gg);
        float o_ = 1.f / (1.f + __expf(-go));
        float cn = f_ * C[b * RNND + unit] + i_ * g_;
        float hn = o_ * tanhf(cn);
        C[b * RNND + unit] = cn;
        H[((size_t)t * 64 + b) * RNND + unit] = hn;
    }
}

__global__ __launch_bounds__(256) void stop_kernel(
    const float* __restrict__ H, const float* __restrict__ sw,
    const float* __restrict__ sb, float* __restrict__ gout)
{
    int row = blockIdx.x * 8 + (threadIdx.x >> 5);
    int lane = threadIdx.x & 31;
    const float* h = H + (size_t)row * RNND;
    float acc = 0.f;
    for (int k = lane; k < RNND; k += 32) acc = fmaf(h[k], sw[k], acc);
#pragma unroll
    for (int o = 16; o; o >>= 1) acc += __shfl_xor_sync(0xffffffffu, acc, o);
    if (lane == 0) {
        int t = row >> 6, b = row & 63;
        gout[b * TDEC + t] = 1.f / (1.f + __expf(-(acc + sb[0])));
    }
}

extern "C" void kernel_launch(void* const* d_in, const int* in_sizes, int n_in,
                              void* d_out, int out_size) {
    const float* enc  = (const float*)d_in[0];
    const float* mel  = (const float*)d_in[1];
    const float* W1   = (const float*)d_in[4];
    const float* b1   = (const float*)d_in[5];
    const float* W2   = (const float*)d_in[6];
    const float* b2   = (const float*)d_in[7];
    const float* Wq   = (const float*)d_in[8];
    const float* Wm   = (const float*)d_in[9];
    const float* av   = (const float*)d_in[10];
    const float* Wih  = (const float*)d_in[11];
    const float* Whh  = (const float*)d_in[12];
    const float* bih  = (const float*)d_in[13];
    const float* bhh  = (const float*)d_in[14];
    const float* melW = (const float*)d_in[15];
    const float* melb = (const float*)d_in[16];
    const float* stW  = (const float*)d_in[17];
    const float* stb  = (const float*)d_in[18];
    float* out = (float*)d_out;

    float *Pin, *P1, *P2, *Q, *PM, *E, *X, *G1, *H, *C;
    cudaGetSymbolAddress((void**)&Pin, g_Pin);
    cudaGetSymbolAddress((void**)&P1,  g_P1);
    cudaGetSymbolAddress((void**)&P2,  g_P2);
    cudaGetSymbolAddress((void**)&Q,   g_Q);
    cudaGetSymbolAddress((void**)&PM,  g_PM);
    cudaGetSymbolAddress((void**)&E,   g_E);
    cudaGetSymbolAddress((void**)&X,   g_X);
    cudaGetSymbolAddress((void**)&G1,  g_G1);
    cudaGetSymbolAddress((void**)&H,   g_H);
    cudaGetSymbolAddress((void**)&C,   g_C);

    zero_kernel<<<(BATCH*RNND + 255)/256, 256>>>(C, BATCH*RNND);
    prep_pin_kernel<<<(ROWS*MELD + 255)/256, 256>>>(mel, Pin);

    // prenet1: [16384,80]@[80,256] -> relu
    sgemm_kernel<<<dim3(2, ROWS/128), 256>>>(Pin, MELD, W1, 256, P1, 256,
        ROWS, 256, MELD, b1, nullptr, 1, 0);
    // prenet2: [16384,256]@[256,256] -> relu
    sgemm_kernel<<<dim3(2, ROWS/128), 256>>>(P1, 256, W2, 256, P2, 256,
        ROWS, 256, 256, b2, nullptr, 1, 0);
    // Q: [16384,256]@[256,128]
    sgemm_kernel<<<dim3(1, ROWS/128), 256>>>(P2, 256, Wq, 128, Q, 128,
        ROWS, 128, 256, nullptr, nullptr, 0, 0);
    // PM: [73728,256]@[256,128]
    sgemm_kernel<<<dim3(1, (BATCH*TENC)/128), 256>>>(enc, 256, Wm, 128, PM, 128,
        BATCH*TENC, 128, 256, nullptr, nullptr, 0, 0);

    att_e_kernel<<<dim3(TENC/64, BATCH), 256>>>(Q, PM, av, E);
    att_softmax_ctx_kernel<<<dim3(TDEC/8, BATCH), 256>>>(E, PM, X, out + ALIGNS_OFF);

    // G1: [16384,1280]@[1280,4096] + b_ih + b_hh
    sgemm_kernel<<<dim3(GATE4/128, ROWS/128), 256>>>(X, KX, Wih, GATE4, G1, GATE4,
        ROWS, GATE4, KX, bih, bhh, 0, 0);

    for (int t = 0; t < TDEC; t++)
        lstm_step_kernel<<<128, 128>>>(G1, Whh, H, C, t);

    // mels: [16384,1024]@[1024,80] + mel_b, permuted to [b][t][m]
    sgemm_kernel<<<dim3(1, ROWS/128), 256>>>(H, RNND, melW, MELD, out, MELD,
        ROWS, MELD, RNND, melb, nullptr, 0, 1);

    stop_kernel<<<ROWS/8, 256>>>(H, stW, stb, out + GATES_OFF);
}